// round 2
// baseline (speedup 1.0000x reference)
#include <cuda_runtime.h>
#include <math.h>

#define EPS 1e-8f
#define B 64
#define N 1024
#define W 128

// Output layout (flattened concat of the 4 outputs)
#define OFF_W    ((size_t)0)
#define OFF_MEM  ((size_t)(B*N))                       // 65536
#define OFF_LINK ((size_t)(B*N) + (size_t)B*N*W)       // 8454144
#define OFF_PREC (OFF_LINK + (size_t)B*N*N)            // 75563008

__device__ __forceinline__ float softplus1(float x) {
    // 1 + log1p(exp(x)), stable
    if (x > 20.f) return 1.f + x;
    return 1.f + log1pf(expf(x));
}
__device__ __forceinline__ float sigmoidf_(float x) {
    return 1.f / (1.f + expf(-x));
}
__device__ __forceinline__ float warp_sum(float v) {
    #pragma unroll
    for (int o = 16; o > 0; o >>= 1) v += __shfl_xor_sync(0xFFFFFFFFu, v, o);
    return v;
}
__device__ __forceinline__ float warp_max(float v) {
    #pragma unroll
    for (int o = 16; o > 0; o >>= 1) v = fmaxf(v, __shfl_xor_sync(0xFFFFFFFFu, v, o));
    return v;
}

// One block per batch. 1024 threads (32 warps).
// Computes c_weights (cosine-sim softmax), w_weights, precedence_new.
__global__ __launch_bounds__(1024) void head_kernel(
    const float* __restrict__ w_key,    // (B,W)
    const float* __restrict__ w_beta,   // (B,1)
    const float* __restrict__ a_gate,   // (B,1)
    const float* __restrict__ w_gate,   // (B,1)
    const float* __restrict__ alloc,    // (B,N)
    const float* __restrict__ memory,   // (B,N,W)
    const float* __restrict__ prec,     // (B,N)
    float* __restrict__ out)            // full output buffer
{
    const int b = blockIdx.x;
    const int tid = threadIdx.x;
    const int lane = tid & 31;
    const int wid  = tid >> 5;

    __shared__ float sk[W];       // key
    __shared__ float ssim[N];     // sims
    __shared__ float sred[32];
    __shared__ float sbr;         // broadcast scalar

    if (tid < W) sk[tid] = w_key[(size_t)b * W + tid];
    __syncthreads();

    // key norm (warp 0)
    if (wid == 0) {
        float s = 0.f;
        #pragma unroll
        for (int c = 0; c < W / 32; c++) {
            float v = sk[lane + 32 * c];
            s += v * v;
        }
        s = warp_sum(s);
        if (lane == 0) sbr = sqrtf(s) + EPS;
    }
    __syncthreads();
    const float knorm = sbr;
    const float beta = softplus1(w_beta[b]);

    // warp-per-row dot products: sim = (m·k) / ((|m|+eps)(|k|+eps)) * beta
    const float4* k4 = (const float4*)sk;
    const float4 kk = k4[lane];
    for (int n = wid; n < N; n += 32) {
        const float4* row = (const float4*)(memory + ((size_t)b * N + n) * W);
        float4 v = row[lane];
        float dot = v.x * kk.x + v.y * kk.y + v.z * kk.z + v.w * kk.w;
        float ss  = v.x * v.x + v.y * v.y + v.z * v.z + v.w * v.w;
        dot = warp_sum(dot);
        ss  = warp_sum(ss);
        if (lane == 0)
            ssim[n] = dot / ((sqrtf(ss) + EPS) * knorm) * beta;
    }
    __syncthreads();

    // softmax over N (each thread owns one element)
    float x = ssim[tid];
    float m = warp_max(x);
    if (lane == 0) sred[wid] = m;
    __syncthreads();
    if (wid == 0) {
        float mm = sred[lane];
        mm = warp_max(mm);
        if (lane == 0) sbr = mm;
    }
    __syncthreads();
    const float mx = sbr;
    float e = expf(x - mx);
    float s = warp_sum(e);
    if (lane == 0) sred[wid] = s;
    __syncthreads();
    if (wid == 0) {
        float ssum = sred[lane];
        ssum = warp_sum(ssum);
        if (lane == 0) sbr = ssum;
    }
    __syncthreads();
    const float inv_sum = 1.f / sbr;
    const float c_w = e * inv_sum;

    // gates
    const float ag = sigmoidf_(a_gate[b]);
    const float wg = sigmoidf_(w_gate[b]);
    const float w = wg * (ag * alloc[(size_t)b * N + tid] + (1.f - ag) * c_w);

    out[OFF_W + (size_t)b * N + tid] = w;

    // sum of w for precedence update
    float ws = warp_sum(w);
    if (lane == 0) sred[wid] = ws;
    __syncthreads();
    if (wid == 0) {
        float t = sred[lane];
        t = warp_sum(t);
        if (lane == 0) sbr = t;
    }
    __syncthreads();
    const float wsum = sbr;
    const float p = prec[(size_t)b * N + tid];
    out[OFF_PREC + (size_t)b * N + tid] = (1.f - wsum) * p + w;
}

// memory passthrough, float4 vectorized
__global__ void copy_kernel(const float4* __restrict__ src, float4* __restrict__ dst, int n4) {
    int idx = blockIdx.x * blockDim.x + threadIdx.x;
    if (idx < n4) dst[idx] = src[idx];
}

// link[b,i,j] = (1 - w[b,i] - w[b,j]) * L[b,i,j] + w[b,i] * p[b,j], diag = 0
// One block handles ROWS_PER_BLK consecutive (b,i) rows within one batch;
// 256 threads x float4 covers N=1024 columns. wj/pj loaded once, reused.
#define ROWS_PER_BLK 2
__global__ __launch_bounds__(256) void link_kernel(
    const float* __restrict__ link_in,   // (B,N,N)
    const float* __restrict__ w,         // w_weights in out buffer (B,N)
    const float* __restrict__ p,         // precedence input (B,N)
    float* __restrict__ link_out)
{
    const int blk = blockIdx.x;                       // (b*N + i0) / ROWS_PER_BLK
    const int row0 = blk * ROWS_PER_BLK;              // b*N + i0
    const int b = row0 >> 10;
    const int i0 = row0 & (N - 1);
    const int tid = threadIdx.x;

    const float4 wj = ((const float4*)(w + (size_t)b * N))[tid];
    const float4 pj = ((const float4*)(p + (size_t)b * N))[tid];
    const int j0 = tid << 2;

    #pragma unroll
    for (int r = 0; r < ROWS_PER_BLK; r++) {
        const int i = i0 + r;
        const size_t rowoff = ((size_t)b * N + i) * N;
        const float wi = __ldg(&w[(size_t)b * N + i]);
        const float one_minus_wi = 1.f - wi;

        const float4 L = ((const float4*)(link_in + rowoff))[tid];

        float4 o;
        o.x = (one_minus_wi - wj.x) * L.x + wi * pj.x;
        o.y = (one_minus_wi - wj.y) * L.y + wi * pj.y;
        o.z = (one_minus_wi - wj.z) * L.z + wi * pj.z;
        o.w = (one_minus_wi - wj.w) * L.w + wi * pj.w;

        if (i >= j0 && i < j0 + 4) ((float*)&o)[i - j0] = 0.f;

        ((float4*)(link_out + rowoff))[tid] = o;
    }
}

extern "C" void kernel_launch(void* const* d_in, const int* in_sizes, int n_in,
                              void* d_out, int out_size) {
    const float* w_key    = (const float*)d_in[0];
    const float* w_beta   = (const float*)d_in[1];
    // d_in[2] = e_vector (unused), d_in[3] = w_vector (unused)
    const float* a_gate   = (const float*)d_in[4];
    const float* w_gate   = (const float*)d_in[5];
    const float* alloc    = (const float*)d_in[6];
    const float* memory   = (const float*)d_in[7];
    const float* link_in  = (const float*)d_in[8];
    const float* prec     = (const float*)d_in[9];
    float* out = (float*)d_out;

    // 1) head: w_weights + precedence_new
    head_kernel<<<B, 1024>>>(w_key, w_beta, a_gate, w_gate, alloc, memory, prec, out);

    // 2) memory passthrough
    const int n4 = (B * N * W) / 4;  // 2097152
    copy_kernel<<<n4 / 256, 256>>>((const float4*)memory, (float4*)(out + OFF_MEM), n4);

    // 3) link update (reads w_weights written by head_kernel; same stream => ordered)
    link_kernel<<<(B * N) / ROWS_PER_BLK, 256>>>(link_in, out + OFF_W, prec, out + OFF_LINK);
}

// round 8
// speedup vs baseline: 1.1580x; 1.1580x over previous
#include <cuda_runtime.h>
#include <math.h>

#define EPS 1e-8f
#define B 64
#define N 1024
#define W 128

// Output layout (flattened concat of the 4 outputs)
#define OFF_W    ((size_t)0)
#define OFF_MEM  ((size_t)(B*N))                       // 65536
#define OFF_LINK ((size_t)(B*N) + (size_t)B*N*W)       // 8454144
#define OFF_PREC (OFF_LINK + (size_t)B*N*N)            // 75563008

__device__ __forceinline__ float softplus1(float x) {
    if (x > 20.f) return 1.f + x;
    return 1.f + log1pf(expf(x));
}
__device__ __forceinline__ float sigmoidf_(float x) {
    return 1.f / (1.f + expf(-x));
}
__device__ __forceinline__ float warp_sum(float v) {
    #pragma unroll
    for (int o = 16; o > 0; o >>= 1) v += __shfl_xor_sync(0xFFFFFFFFu, v, o);
    return v;
}
__device__ __forceinline__ float warp_max(float v) {
    #pragma unroll
    for (int o = 16; o > 0; o >>= 1) v = fmaxf(v, __shfl_xor_sync(0xFFFFFFFFu, v, o));
    return v;
}

// ---------------------------------------------------------------------------
// sim_kernel: cosine similarity * beta for all (b,n) rows, fused with the
// memory passthrough (each warp writes the row it just read to out+OFF_MEM).
// Sims are stashed in the out+OFF_PREC region (finish_kernel reads each
// element in the same thread that then overwrites it with precedence_new).
// Grid: B*16 blocks of 256 threads (8 warps). Each block: 64 rows of one batch.
// ---------------------------------------------------------------------------
#define SIM_BLOCKS_PER_B 16
#define SIM_ROWS_PER_BLOCK (N / SIM_BLOCKS_PER_B)   // 64
#define SIM_ROWS_PER_WARP  (SIM_ROWS_PER_BLOCK / 8) // 8

__global__ __launch_bounds__(256) void sim_kernel(
    const float* __restrict__ w_key,    // (B,W)
    const float* __restrict__ w_beta,   // (B,1)
    const float* __restrict__ memory,   // (B,N,W)
    float* __restrict__ out)            // full out buffer
{
    const int blk = blockIdx.x;
    const int b = blk / SIM_BLOCKS_PER_B;
    const int n0 = (blk % SIM_BLOCKS_PER_B) * SIM_ROWS_PER_BLOCK;
    const int tid = threadIdx.x;
    const int lane = tid & 31;
    const int wid  = tid >> 5;

    __shared__ float sk[W];
    __shared__ float s_scale;   // beta / knorm

    if (tid < W) sk[tid] = w_key[(size_t)b * W + tid];
    __syncthreads();

    if (wid == 0) {
        float s = 0.f;
        #pragma unroll
        for (int c = 0; c < W / 32; c++) {
            float v = sk[lane + 32 * c];
            s += v * v;
        }
        s = warp_sum(s);
        if (lane == 0) {
            float knorm = sqrtf(s) + EPS;
            s_scale = softplus1(w_beta[b]) / knorm;
        }
    }
    __syncthreads();
    const float scale = s_scale;

    const float4 kk = ((const float4*)sk)[lane];
    float* out_mem = out + OFF_MEM;
    float* sim_stash = out + OFF_PREC;   // temporary home for sims

    #pragma unroll
    for (int r = 0; r < SIM_ROWS_PER_WARP; r++) {
        const int n = n0 + wid * SIM_ROWS_PER_WARP + r;
        const size_t roff = ((size_t)b * N + n) * W;
        float4 v = ((const float4*)(memory + roff))[lane];

        // fused passthrough write
        ((float4*)(out_mem + roff))[lane] = v;

        float dot = v.x * kk.x + v.y * kk.y + v.z * kk.z + v.w * kk.w;
        float ss  = v.x * v.x + v.y * v.y + v.z * v.z + v.w * v.w;
        dot = warp_sum(dot);
        ss  = warp_sum(ss);
        if (lane == 0)
            sim_stash[(size_t)b * N + n] = dot / (sqrtf(ss) + EPS) * scale;
    }
}

// ---------------------------------------------------------------------------
// finish_kernel: softmax over sims, gates, w_weights, precedence_new.
// One block per batch, 1024 threads. Reads sim from out+OFF_PREC, then
// overwrites that same element with precedence_new (read-before-write per
// thread; no cross-thread hazard).
// ---------------------------------------------------------------------------
__global__ __launch_bounds__(1024) void finish_kernel(
    const float* __restrict__ a_gate,   // (B,1)
    const float* __restrict__ w_gate,   // (B,1)
    const float* __restrict__ alloc,    // (B,N)
    const float* __restrict__ prec,     // (B,N)
    float* __restrict__ out)
{
    const int b = blockIdx.x;
    const int tid = threadIdx.x;
    const int lane = tid & 31;
    const int wid  = tid >> 5;

    __shared__ float sred[32];
    __shared__ float sbr;

    float x = out[OFF_PREC + (size_t)b * N + tid];   // stashed sim

    // block max
    float m = warp_max(x);
    if (lane == 0) sred[wid] = m;
    __syncthreads();
    if (wid == 0) {
        float mm = warp_max(sred[lane]);
        if (lane == 0) sbr = mm;
    }
    __syncthreads();
    const float mx = sbr;

    // block sum of exp
    float e = expf(x - mx);
    float s = warp_sum(e);
    if (lane == 0) sred[wid] = s;
    __syncthreads();
    if (wid == 0) {
        float t = warp_sum(sred[lane]);
        if (lane == 0) sbr = t;
    }
    __syncthreads();
    const float c_w = e / sbr;

    const float ag = sigmoidf_(a_gate[b]);
    const float wg = sigmoidf_(w_gate[b]);
    const float w = wg * (ag * alloc[(size_t)b * N + tid] + (1.f - ag) * c_w);

    out[OFF_W + (size_t)b * N + tid] = w;

    // block sum of w for precedence update
    float ws = warp_sum(w);
    if (lane == 0) sred[wid] = ws;
    __syncthreads();
    if (wid == 0) {
        float t = warp_sum(sred[lane]);
        if (lane == 0) sbr = t;
    }
    __syncthreads();
    const float wsum = sbr;
    const float p = prec[(size_t)b * N + tid];
    out[OFF_PREC + (size_t)b * N + tid] = (1.f - wsum) * p + w;
}

// ---------------------------------------------------------------------------
// link_kernel: link[b,i,j] = (1 - w_i - w_j)*L[b,i,j] + w_i*p_j, diag = 0
// One block handles 4 consecutive rows of one batch; loads front-batched
// (MLP_p1 = 4) for latency hiding. 256 threads x float4 covers N = 1024.
// ---------------------------------------------------------------------------
#define ROWS_PER_BLK 4
__global__ __launch_bounds__(256) void link_kernel(
    const float* __restrict__ link_in,   // (B,N,N)
    const float* __restrict__ w,         // w_weights (in out buffer)
    const float* __restrict__ p,         // precedence input
    float* __restrict__ link_out)
{
    const int blk = blockIdx.x;
    const int row0 = blk * ROWS_PER_BLK;         // b*N + i0
    const int b = row0 >> 10;
    const int i0 = row0 & (N - 1);
    const int tid = threadIdx.x;

    const float4 wj = ((const float4*)(w + (size_t)b * N))[tid];
    const float4 pj = ((const float4*)(p + (size_t)b * N))[tid];
    const int j0 = tid << 2;

    // front-batched loads: 4 independent LDG.128 in flight
    float4 L[ROWS_PER_BLK];
    float wi[ROWS_PER_BLK];
    #pragma unroll
    for (int r = 0; r < ROWS_PER_BLK; r++) {
        const size_t rowoff = ((size_t)row0 + r) * N;
        L[r] = ((const float4*)(link_in + rowoff))[tid];
        wi[r] = __ldg(&w[(size_t)b * N + i0 + r]);
    }

    #pragma unroll
    for (int r = 0; r < ROWS_PER_BLK; r++) {
        const int i = i0 + r;
        const float omwi = 1.f - wi[r];
        float4 o;
        o.x = (omwi - wj.x) * L[r].x + wi[r] * pj.x;
        o.y = (omwi - wj.y) * L[r].y + wi[r] * pj.y;
        o.z = (omwi - wj.z) * L[r].z + wi[r] * pj.z;
        o.w = (omwi - wj.w) * L[r].w + wi[r] * pj.w;
        if (i >= j0 && i < j0 + 4) ((float*)&o)[i - j0] = 0.f;
        ((float4*)(link_out + ((size_t)row0 + r) * N))[tid] = o;
    }
}

extern "C" void kernel_launch(void* const* d_in, const int* in_sizes, int n_in,
                              void* d_out, int out_size) {
    const float* w_key    = (const float*)d_in[0];
    const float* w_beta   = (const float*)d_in[1];
    // d_in[2] = e_vector (unused), d_in[3] = w_vector (unused)
    const float* a_gate   = (const float*)d_in[4];
    const float* w_gate   = (const float*)d_in[5];
    const float* alloc    = (const float*)d_in[6];
    const float* memory   = (const float*)d_in[7];
    const float* link_in  = (const float*)d_in[8];
    const float* prec     = (const float*)d_in[9];
    float* out = (float*)d_out;

    // 1) similarities (stashed in out+OFF_PREC) + fused memory passthrough
    sim_kernel<<<B * SIM_BLOCKS_PER_B, 256>>>(w_key, w_beta, memory, out);

    // 2) softmax + gates + w_weights + precedence_new (overwrites stash)
    finish_kernel<<<B, 1024>>>(a_gate, w_gate, alloc, prec, out);

    // 3) link update (reads w_weights written by finish_kernel; same stream)
    link_kernel<<<(B * N) / ROWS_PER_BLK, 256>>>(link_in, out + OFF_W, prec, out + OFF_LINK);
}